// round 5
// baseline (speedup 1.0000x reference)
#include <cuda_runtime.h>

// BloomStageLoss: label-smoothed CE + transition penalty, reduced to scalar.
// inputs:  d_in[0] = float32 [B,5], d_in[1] = int32 [B]; output: float32 [1]
//
// loss_row = lse - 0.875*x_t - 0.025*sum(x)
//          + 0.1*(2 - (2*e_t + 1.5*(e_{t-1}+e_{t+1}) + (e_{t-2}+e_{t+2}))/se)

#define TGT_W     0.875f
#define SMOOTH_W  0.025f
#define TPEN      0.1f

__device__ float        g_acc;        // zero-init at module load; reset by last block each replay
__device__ unsigned int g_count;

// Returns lse - 0.875*x_t - 0.1*u/se  (caller adds -0.025*grand_sum and +0.2/row)
__device__ __forceinline__ float row_core(float x0, float x1, float x2, float x3, float x4, int t) {
    float e0 = __expf(x0), e1 = __expf(x1), e2 = __expf(x2), e3 = __expf(x3), e4 = __expf(x4);
    float se  = ((e0 + e1) + (e2 + e3)) + e4;
    float lse = __logf(se);
    float p02 = e0 + e2, p13 = e1 + e3, p24 = e2 + e4, p04 = e0 + e4;
    float xt = (t == 0) ? x0  : (t == 1) ? x1  : (t == 2) ? x2  : (t == 3) ? x3  : x4;
    float et = (t == 0) ? e0  : (t == 1) ? e1  : (t == 2) ? e2  : (t == 3) ? e3  : e4;
    float a  = (t == 0) ? e1  : (t == 1) ? p02 : (t == 2) ? p13 : (t == 3) ? p24 : e3;  // e_{t-1}+e_{t+1}
    float b  = (t == 0) ? e2  : (t == 1) ? e3  : (t == 2) ? p04 : (t == 3) ? e1  : e2;  // e_{t-2}+e_{t+2}
    float u  = fmaf(2.0f, et, fmaf(1.5f, a, b));
    return fmaf(-TPEN, u * __frcp_rn(se), fmaf(-TGT_W, xt, lse));
}

__device__ __forceinline__ float sum4(float4 v) {
    return (v.x + v.y) + (v.z + v.w);
}

// Process 5 consecutive float4 (= 4 rows) given 4 targets; returns partial loss
// (minus the -0.025*sum and +0.2/row terms, handled by caller).
__device__ __forceinline__ float quad_core(float4 a, float4 b, float4 c, float4 d, float4 e,
                                           int t0, int t1, int t2, int t3, float* gs) {
    *gs += sum4(a) + sum4(b) + sum4(c) + sum4(d) + sum4(e);
    float acc;
    acc  = row_core(a.x, a.y, a.z, a.w, b.x, t0);
    acc += row_core(b.y, b.z, b.w, c.x, c.y, t1);
    acc += row_core(c.z, c.w, d.x, d.y, d.z, t2);
    acc += row_core(d.w, e.x, e.y, e.z, e.w, t3);
    return acc;
}

__global__ __launch_bounds__(256)
void bloom_loss_kernel(const float4* __restrict__ in4,
                       const int4*   __restrict__ tgt4,
                       float* __restrict__ out,
                       int nocts, int n, float inv_b) {
    int tq = blockIdx.x * blockDim.x + threadIdx.x;   // one oct = 8 rows
    float acc = 0.0f;
    if (tq < nocts) {
        // 8 rows = 40 floats = 10 x float4 ; targets = 2 x int4. All loads front-batched.
        const float4* p = in4 + (size_t)tq * 10;
        float4 f0 = p[0], f1 = p[1], f2 = p[2], f3 = p[3], f4 = p[4];
        float4 f5 = p[5], f6 = p[6], f7 = p[7], f8 = p[8], f9 = p[9];
        int4 ta = tgt4[tq * 2 + 0];
        int4 tb = tgt4[tq * 2 + 1];
        float gs = 0.0f;
        acc  = quad_core(f0, f1, f2, f3, f4, ta.x, ta.y, ta.z, ta.w, &gs);
        acc += quad_core(f5, f6, f7, f8, f9, tb.x, tb.y, tb.z, tb.w, &gs);
        acc = fmaf(-SMOOTH_W, gs, acc) + (8.0f * TPEN * 2.0f);   // +0.2 per row, 8 rows
    }
    // tail rows (n % 8): one thread; not hit when n is a multiple of 8
    if (blockIdx.x == 0 && threadIdx.x == 0) {
        const float* in_s  = (const float*)in4;
        const int*   tgt_s = (const int*)tgt4;
        for (int i = nocts * 8; i < n; i++) {
            const float* x = in_s + (size_t)i * 5;
            float s = ((x[0] + x[1]) + (x[2] + x[3])) + x[4];
            acc += row_core(x[0], x[1], x[2], x[3], x[4], tgt_s[i]);
            acc = fmaf(-SMOOTH_W, s, acc) + (TPEN * 2.0f);
        }
    }
    // warp reduce
    #pragma unroll
    for (int o = 16; o > 0; o >>= 1) acc += __shfl_xor_sync(0xFFFFFFFFu, acc, o);
    __shared__ float ssum[8];
    int lane = threadIdx.x & 31;
    int wid  = threadIdx.x >> 5;
    if (lane == 0) ssum[wid] = acc;
    __syncthreads();
    if (wid == 0) {
        float v = (lane < 8) ? ssum[lane] : 0.0f;
        #pragma unroll
        for (int o = 4; o > 0; o >>= 1) v += __shfl_xor_sync(0xFFFFFFFFu, v, o);
        if (lane == 0) {
            atomicAdd(&g_acc, v);
            __threadfence();
            unsigned int done = atomicAdd(&g_count, 1u);
            if (done == gridDim.x - 1) {
                float tot = atomicAdd(&g_acc, 0.0f);   // coherent read after all adds
                out[0] = tot * inv_b;
                g_acc   = 0.0f;                        // reset for next graph replay
                __threadfence();
                g_count = 0u;
            }
        }
    }
}

extern "C" void kernel_launch(void* const* d_in, const int* in_sizes, int n_in,
                              void* d_out, int out_size) {
    const float* inputs  = (const float*)d_in[0];
    const int*   targets = (const int*)d_in[1];
    float* out = (float*)d_out;

    int n = in_sizes[1];            // B rows
    int nocts = n >> 3;
    float inv_b = 1.0f / (float)n;

    int blocks = (nocts > 0) ? (nocts + 255) / 256 : 1;
    bloom_loss_kernel<<<blocks, 256>>>((const float4*)inputs,
                                       (const int4*)targets,
                                       out, nocts, n, inv_b);
}

// round 6
// speedup vs baseline: 1.0982x; 1.0982x over previous
#include <cuda_runtime.h>

// BloomStageLoss: label-smoothed CE + transition penalty, reduced to scalar.
// inputs:  d_in[0] = float32 [B,5], d_in[1] = int32 [B]; output: float32 [1]
//
// loss_row = lse - 0.875*x_t - 0.025*sum(x)
//          + 0.1*(2 - (2*e_t + 1.5*(e_{t-1}+e_{t+1}) + (e_{t-2}+e_{t+2}))/se)

#define TGT_W     0.875f
#define SMOOTH_W  0.025f
#define TPEN      0.1f

__device__ float        g_acc;        // zero-init at module load; reset by last block each replay
__device__ unsigned int g_count;

// Returns lse - 0.875*x_t - 0.1*u/se  (caller adds -0.025*grand_sum and +0.2/row)
__device__ __forceinline__ float row_core(float x0, float x1, float x2, float x3, float x4, int t) {
    float e0 = __expf(x0), e1 = __expf(x1), e2 = __expf(x2), e3 = __expf(x3), e4 = __expf(x4);
    float se  = ((e0 + e1) + (e2 + e3)) + e4;
    float lse = __logf(se);
    float p02 = e0 + e2, p13 = e1 + e3, p24 = e2 + e4, p04 = e0 + e4;
    float xt = (t == 0) ? x0  : (t == 1) ? x1  : (t == 2) ? x2  : (t == 3) ? x3  : x4;
    float et = (t == 0) ? e0  : (t == 1) ? e1  : (t == 2) ? e2  : (t == 3) ? e3  : e4;
    float a  = (t == 0) ? e1  : (t == 1) ? p02 : (t == 2) ? p13 : (t == 3) ? p24 : e3;  // e_{t-1}+e_{t+1}
    float b  = (t == 0) ? e2  : (t == 1) ? e3  : (t == 2) ? p04 : (t == 3) ? e1  : e2;  // e_{t-2}+e_{t+2}
    float u  = fmaf(2.0f, et, fmaf(1.5f, a, b));
    return fmaf(-TPEN, u * __frcp_rn(se), fmaf(-TGT_W, xt, lse));
}

__device__ __forceinline__ float sum4(float4 v) { return (v.x + v.y) + (v.z + v.w); }

__global__ __launch_bounds__(256)
void bloom_loss_kernel(const float4* __restrict__ in4,
                       const int4*   __restrict__ tgt4,
                       float* __restrict__ out,
                       int nquads, int n, float inv_b) {
    // Warp-local staging: each warp owns 160 float4 (= its 32 quads of 4 rows).
    __shared__ float4 s4[8 * 160];          // 20480 B

    int lane = threadIdx.x & 31;
    int wid  = threadIdx.x >> 5;
    int gw   = blockIdx.x * 8 + wid;        // global warp id
    int q    = gw * 32 + lane;              // this thread's quad (4 rows)
    int fbase = gw * 160;                   // float4 base of this warp's tile
    int flim  = nquads * 5;                 // total float4 count (n%4==0 case)
    float4* ws = s4 + wid * 160;

    // Coalesced global -> smem: 5 unit-stride LDG.128 per thread (4 wf/instr).
    #pragma unroll
    for (int k = 0; k < 5; k++) {
        int idx = k * 32 + lane;
        int g = fbase + idx;
        ws[idx] = (g < flim) ? in4[g] : make_float4(0.f, 0.f, 0.f, 0.f);
    }
    int4 tg = (q < nquads) ? tgt4[q] : make_int4(0, 0, 0, 0);
    __syncwarp();

    float acc = 0.0f;
    if (q < nquads) {
        float4 a = ws[lane * 5 + 0];
        float4 b = ws[lane * 5 + 1];
        float4 c = ws[lane * 5 + 2];
        float4 d = ws[lane * 5 + 3];
        float4 e = ws[lane * 5 + 4];
        float gs = sum4(a) + sum4(b) + sum4(c) + sum4(d) + sum4(e);
        acc  = row_core(a.x, a.y, a.z, a.w, b.x, tg.x);
        acc += row_core(b.y, b.z, b.w, c.x, c.y, tg.y);
        acc += row_core(c.z, c.w, d.x, d.y, d.z, tg.z);
        acc += row_core(d.w, e.x, e.y, e.z, e.w, tg.w);
        acc = fmaf(-SMOOTH_W, gs, acc) + (4.0f * TPEN * 2.0f);   // +0.2 per row
    }
    // tail rows (n % 4): one thread; not hit when n is a multiple of 4
    if (blockIdx.x == 0 && threadIdx.x == 0) {
        const float* in_s  = (const float*)in4;
        const int*   tgt_s = (const int*)tgt4;
        for (int i = nquads * 4; i < n; i++) {
            const float* x = in_s + (size_t)i * 5;
            float s = ((x[0] + x[1]) + (x[2] + x[3])) + x[4];
            acc += row_core(x[0], x[1], x[2], x[3], x[4], tgt_s[i]);
            acc = fmaf(-SMOOTH_W, s, acc) + (TPEN * 2.0f);
        }
    }
    // warp reduce
    #pragma unroll
    for (int o = 16; o > 0; o >>= 1) acc += __shfl_xor_sync(0xFFFFFFFFu, acc, o);
    __shared__ float ssum[8];
    if (lane == 0) ssum[wid] = acc;
    __syncthreads();
    if (wid == 0) {
        float v = (lane < 8) ? ssum[lane] : 0.0f;
        #pragma unroll
        for (int o = 4; o > 0; o >>= 1) v += __shfl_xor_sync(0xFFFFFFFFu, v, o);
        if (lane == 0) {
            atomicAdd(&g_acc, v);
            __threadfence();
            unsigned int done = atomicAdd(&g_count, 1u);
            if (done == gridDim.x - 1) {
                float tot = atomicAdd(&g_acc, 0.0f);   // coherent read after all adds
                out[0] = tot * inv_b;
                g_acc   = 0.0f;                        // reset for next graph replay
                __threadfence();
                g_count = 0u;
            }
        }
    }
}

extern "C" void kernel_launch(void* const* d_in, const int* in_sizes, int n_in,
                              void* d_out, int out_size) {
    const float* inputs  = (const float*)d_in[0];
    const int*   targets = (const int*)d_in[1];
    float* out = (float*)d_out;

    int n = in_sizes[1];            // B rows
    int nquads = n >> 2;
    float inv_b = 1.0f / (float)n;

    int blocks = (nquads > 0) ? (nquads + 255) / 256 : 1;
    bloom_loss_kernel<<<blocks, 256>>>((const float4*)inputs,
                                       (const int4*)targets,
                                       out, nquads, n, inv_b);
}